// round 1
// baseline (speedup 1.0000x reference)
#include <cuda_runtime.h>

// LIF scan: mem = 0.25*mem + x[t]; spk = (mem >= 1); mem -= spk.
// Shape (T=100, 32, 16384) f32. One thread owns 4 neurons (float4 lanes),
// mem lives in registers, x streamed in / spikes streamed out coalesced.

#define T_STEPS 100
#define N_NEUR  (32 * 16384)      // 524288
#define N_VEC   (N_NEUR / 4)      // 131072 float4 lanes

__global__ void __launch_bounds__(256) lif_kernel(const float4* __restrict__ x,
                                                  float4* __restrict__ out) {
    const int i = blockIdx.x * blockDim.x + threadIdx.x;   // 0..N_VEC-1
    const float beta = 0.25f;

    float4 mem = make_float4(0.f, 0.f, 0.f, 0.f);

    const float4* xp = x + i;
    float4* op = out + i;

#pragma unroll 4
    for (int t = 0; t < T_STEPS; ++t) {
        float4 xt = xp[(size_t)t * N_VEC];

        float4 spk;

        mem.x = fmaf(beta, mem.x, xt.x);
        spk.x = (mem.x >= 1.0f) ? 1.0f : 0.0f;
        mem.x -= spk.x;

        mem.y = fmaf(beta, mem.y, xt.y);
        spk.y = (mem.y >= 1.0f) ? 1.0f : 0.0f;
        mem.y -= spk.y;

        mem.z = fmaf(beta, mem.z, xt.z);
        spk.z = (mem.z >= 1.0f) ? 1.0f : 0.0f;
        mem.z -= spk.z;

        mem.w = fmaf(beta, mem.w, xt.w);
        spk.w = (mem.w >= 1.0f) ? 1.0f : 0.0f;
        mem.w -= spk.w;

        op[(size_t)t * N_VEC] = spk;
    }
}

extern "C" void kernel_launch(void* const* d_in, const int* in_sizes, int n_in,
                              void* d_out, int out_size) {
    const float4* x = (const float4*)d_in[0];
    float4* out = (float4*)d_out;
    lif_kernel<<<N_VEC / 256, 256>>>(x, out);
}

// round 6
// speedup vs baseline: 1.0874x; 1.0874x over previous
#include <cuda_runtime.h>

// LIF scan: mem = 0.25*mem + x[t]; spk = (mem >= 1); mem -= spk.
// Shape (T=100, 32, 16384) f32. One thread owns 4 neurons (float4 lanes),
// mem in registers, x streamed in / spikes streamed out coalesced.
// v2: streaming cache hints (__ldcs/__stcs) — every byte touched once, so
// evict-first in L1/L2; software-pipelined prefetch keeps loads a full
// timestep ahead of the mem-dependency chain.

#define T_STEPS 100
#define N_NEUR  (32 * 16384)      // 524288
#define N_VEC   (N_NEUR / 4)      // 131072 float4 lanes

__global__ void __launch_bounds__(256) lif_kernel(const float4* __restrict__ x,
                                                  float4* __restrict__ out) {
    const int i = blockIdx.x * blockDim.x + threadIdx.x;   // 0..N_VEC-1
    const float beta = 0.25f;

    float4 mem = make_float4(0.f, 0.f, 0.f, 0.f);

    const float4* xp = x + i;
    float4* op = out + i;

    // Prefetch t=0
    float4 xt = __ldcs(xp);

#pragma unroll 4
    for (int t = 0; t < T_STEPS - 1; ++t) {
        // Load t+1 before the dependent compute/store of t.
        float4 xn = __ldcs(xp + (size_t)(t + 1) * N_VEC);

        float4 spk;
        mem.x = fmaf(beta, mem.x, xt.x);
        spk.x = (mem.x >= 1.0f) ? 1.0f : 0.0f;
        mem.x -= spk.x;

        mem.y = fmaf(beta, mem.y, xt.y);
        spk.y = (mem.y >= 1.0f) ? 1.0f : 0.0f;
        mem.y -= spk.y;

        mem.z = fmaf(beta, mem.z, xt.z);
        spk.z = (mem.z >= 1.0f) ? 1.0f : 0.0f;
        mem.z -= spk.z;

        mem.w = fmaf(beta, mem.w, xt.w);
        spk.w = (mem.w >= 1.0f) ? 1.0f : 0.0f;
        mem.w -= spk.w;

        __stcs(op + (size_t)t * N_VEC, spk);
        xt = xn;
    }

    // Final timestep (no prefetch)
    {
        float4 spk;
        mem.x = fmaf(beta, mem.x, xt.x);
        spk.x = (mem.x >= 1.0f) ? 1.0f : 0.0f;
        mem.x -= spk.x;

        mem.y = fmaf(beta, mem.y, xt.y);
        spk.y = (mem.y >= 1.0f) ? 1.0f : 0.0f;
        mem.y -= spk.y;

        mem.z = fmaf(beta, mem.z, xt.z);
        spk.z = (mem.z >= 1.0f) ? 1.0f : 0.0f;
        mem.z -= spk.z;

        mem.w = fmaf(beta, mem.w, xt.w);
        spk.w = (mem.w >= 1.0f) ? 1.0f : 0.0f;
        mem.w -= spk.w;

        __stcs(op + (size_t)(T_STEPS - 1) * N_VEC, spk);
    }
}

extern "C" void kernel_launch(void* const* d_in, const int* in_sizes, int n_in,
                              void* d_out, int out_size) {
    const float4* x = (const float4*)d_in[0];
    float4* out = (float4*)d_out;
    lif_kernel<<<N_VEC / 256, 256>>>(x, out);
}